// round 1
// baseline (speedup 1.0000x reference)
#include <cuda_runtime.h>

typedef unsigned long long ULL;

#define N_   16
#define C_   384
#define S_   1024
#define NH_  6
#define D_   64
#define C3_  1152
#define M_   (N_*S_)

// ---------------- scratch (device globals; no allocation) ----------------
__device__ float g_wqkvT[C_*C3_];         // [384][1152]
__device__ float g_woutT[C_*C_];          // [384][384]
__device__ float g_q[N_*NH_*S_*D_];       // [n*6+h][s][d], pre-scaled
__device__ float g_k[N_*NH_*S_*D_];
__device__ float g_v[N_*NH_*S_*D_];
__device__ float g_ao[N_*S_*C_];          // attention output, [n][s][c]

// ---------------- packed f32x2 helpers (full-rate fp32 on sm_103a) -------
__device__ __forceinline__ ULL pack2(float lo, float hi) {
    ULL r; asm("mov.b64 %0, {%1, %2};" : "=l"(r) : "f"(lo), "f"(hi)); return r;
}
__device__ __forceinline__ float2 unpack2(ULL a) {
    float2 f; asm("mov.b64 {%0, %1}, %2;" : "=f"(f.x), "=f"(f.y) : "l"(a)); return f;
}
__device__ __forceinline__ ULL fma2(ULL a, ULL b, ULL c) {
    ULL d; asm("fma.rn.f32x2 %0, %1, %2, %3;" : "=l"(d) : "l"(a), "l"(b), "l"(c)); return d;
}
__device__ __forceinline__ ULL mul2(ULL a, ULL b) {
    ULL d; asm("mul.rn.f32x2 %0, %1, %2;" : "=l"(d) : "l"(a), "l"(b)); return d;
}
__device__ __forceinline__ ULL add2(ULL a, ULL b) {
    ULL d; asm("add.rn.f32x2 %0, %1, %2;" : "=l"(d) : "l"(a), "l"(b)); return d;
}

// ---------------- weight transposes ----------------
__global__ void transpose_wqkv(const float* __restrict__ w) {
    int idx = blockIdx.x * 256 + threadIdx.x;
    if (idx < C3_ * C_) {
        int r = idx / C_, k = idx % C_;
        g_wqkvT[k * C3_ + r] = w[idx];
    }
}
__global__ void transpose_wout(const float* __restrict__ w) {
    int idx = blockIdx.x * 256 + threadIdx.x;
    if (idx < C_ * C_) {
        int c = idx / C_, k = idx % C_;
        g_woutT[k * C_ + c] = w[idx];
    }
}

// ---------------- QKV projection ----------------
// out[m, r] = sum_k tokens[m,k] * w_qkv[r,k]; tokens[m,k] = x[n, k, s] (m=n*S+s)
// Tile: BM=64 (m), BN=128 (r), BK=16; 256 threads; each thread 4m x 8r via f32x2.
__global__ __launch_bounds__(256) void qkv_gemm(const float* __restrict__ x) {
    __shared__ float As[16][64];
    __shared__ float Bs[16][128];

    int tid = threadIdx.x;
    int m0 = blockIdx.y * 64;
    int r0 = blockIdx.x * 128;
    int n  = m0 / S_;            // 64 | 1024 => constant within block
    int s0 = m0 % S_;
    int ty = tid / 16;           // 0..15 -> m groups of 4
    int tx = tid % 16;           // 0..15 -> r groups of 8

    ULL acc[4][4];
    #pragma unroll
    for (int i = 0; i < 4; i++)
        #pragma unroll
        for (int j = 0; j < 4; j++) acc[i][j] = 0ull;

    for (int k0 = 0; k0 < C_; k0 += 16) {
        __syncthreads();
        { // A tile: 64x16, coalesced along s
            int m4 = tid % 16;
            int kk = tid / 16;
            const float* src = x + (size_t)n * C_ * S_ + (size_t)(k0 + kk) * S_ + s0 + m4 * 4;
            *(float4*)&As[kk][m4 * 4] = *(const float4*)src;
        }
        { // B tile: 16x128, coalesced along r
            int r4 = tid % 32;
            int kk = tid / 32;
            #pragma unroll
            for (int p = 0; p < 2; p++) {
                const float* src = g_wqkvT + (size_t)(k0 + kk + p * 8) * C3_ + r0 + r4 * 4;
                *(float4*)&Bs[kk + p * 8][r4 * 4] = *(const float4*)src;
            }
        }
        __syncthreads();

        #pragma unroll
        for (int k = 0; k < 16; k++) {
            float4 a4 = *(const float4*)&As[k][ty * 4];
            ULL ad0 = pack2(a4.x, a4.x), ad1 = pack2(a4.y, a4.y);
            ULL ad2 = pack2(a4.z, a4.z), ad3 = pack2(a4.w, a4.w);
            const ULL* brow = (const ULL*)&Bs[k][tx * 8];
            ULL b0 = brow[0], b1 = brow[1], b2 = brow[2], b3 = brow[3];
            acc[0][0] = fma2(ad0, b0, acc[0][0]); acc[0][1] = fma2(ad0, b1, acc[0][1]);
            acc[0][2] = fma2(ad0, b2, acc[0][2]); acc[0][3] = fma2(ad0, b3, acc[0][3]);
            acc[1][0] = fma2(ad1, b0, acc[1][0]); acc[1][1] = fma2(ad1, b1, acc[1][1]);
            acc[1][2] = fma2(ad1, b2, acc[1][2]); acc[1][3] = fma2(ad1, b3, acc[1][3]);
            acc[2][0] = fma2(ad2, b0, acc[2][0]); acc[2][1] = fma2(ad2, b1, acc[2][1]);
            acc[2][2] = fma2(ad2, b2, acc[2][2]); acc[2][3] = fma2(ad2, b3, acc[2][3]);
            acc[3][0] = fma2(ad3, b0, acc[3][0]); acc[3][1] = fma2(ad3, b1, acc[3][1]);
            acc[3][2] = fma2(ad3, b2, acc[3][2]); acc[3][3] = fma2(ad3, b3, acc[3][3]);
        }
    }

    const float scale = 0.125f;  // 1/sqrt(64), folded into Q
    #pragma unroll
    for (int mi = 0; mi < 4; mi++) {
        int s = s0 + ty * 4 + mi;
        #pragma unroll
        for (int rp = 0; rp < 4; rp++) {
            float2 v = unpack2(acc[mi][rp]);
            int rbase = r0 + tx * 8 + rp * 2;
            #pragma unroll
            for (int lane = 0; lane < 2; lane++) {
                int r = rbase + lane;
                int t = r / C_;
                int f = r % C_;
                int h = f / D_;
                int d = f % D_;
                float val = lane ? v.y : v.x;
                float* dst;
                if (t == 0)      { dst = g_q; val *= scale; }
                else if (t == 1) { dst = g_k; }
                else             { dst = g_v; }
                dst[(((size_t)(n * NH_ + h)) * S_ + s) * D_ + d] = val;
            }
        }
    }
}

// ---------------- flash attention ----------------
// One thread = one query row. Q and O in registers (f32x2), K/V tiles (32 keys)
// in smem (broadcast LDS), scores staged in padded smem, online softmax.
__global__ __launch_bounds__(128) void attn_kernel() {
    __shared__ float Ks[32][64];
    __shared__ float Vs[32][64];
    __shared__ float Sc[128][33];   // padded: bank-conflict-free per-thread rows

    int nh  = blockIdx.y;           // n*6+h
    int tid = threadIdx.x;
    int q_idx = blockIdx.x * 128 + tid;

    const float* qptr = g_q + ((size_t)nh * S_ + q_idx) * D_;
    ULL q2[32];
    #pragma unroll
    for (int i = 0; i < 16; i++) {
        float4 t4 = *(const float4*)(qptr + i * 4);
        q2[2 * i]     = pack2(t4.x, t4.y);
        q2[2 * i + 1] = pack2(t4.z, t4.w);
    }

    ULL o2[32];
    #pragma unroll
    for (int i = 0; i < 32; i++) o2[i] = 0ull;
    float mrun = -1e30f, lrun = 0.0f;

    const float* kbase = g_k + (size_t)nh * S_ * D_;
    const float* vbase = g_v + (size_t)nh * S_ * D_;

    for (int kt = 0; kt < 32; kt++) {
        __syncthreads();
        #pragma unroll
        for (int i = 0; i < 4; i++) {
            int f = i * 128 + tid;
            int row = f >> 4, c4 = f & 15;
            size_t g = (size_t)(kt * 32 + row) * D_ + c4 * 4;
            *(float4*)&Ks[row][c4 * 4] = *(const float4*)(kbase + g);
            *(float4*)&Vs[row][c4 * 4] = *(const float4*)(vbase + g);
        }
        __syncthreads();

        float tmax = -1e30f;
        #pragma unroll 4
        for (int j = 0; j < 32; j++) {
            const ULL* kr = (const ULL*)&Ks[j][0];
            ULL a0 = 0ull, a1 = 0ull, a2 = 0ull, a3 = 0ull;
            #pragma unroll
            for (int i = 0; i < 32; i += 4) {
                a0 = fma2(q2[i],     kr[i],     a0);
                a1 = fma2(q2[i + 1], kr[i + 1], a1);
                a2 = fma2(q2[i + 2], kr[i + 2], a2);
                a3 = fma2(q2[i + 3], kr[i + 3], a3);
            }
            ULL at = add2(add2(a0, a1), add2(a2, a3));
            float2 u = unpack2(at);
            float sj = u.x + u.y;
            Sc[tid][j] = sj;
            tmax = fmaxf(tmax, sj);
        }

        float mnew = fmaxf(mrun, tmax);
        float corr = __expf(mrun - mnew);
        lrun *= corr;
        ULL cd = pack2(corr, corr);
        #pragma unroll
        for (int i = 0; i < 32; i++) o2[i] = mul2(o2[i], cd);

        #pragma unroll 4
        for (int j = 0; j < 32; j++) {
            float p = __expf(Sc[tid][j] - mnew);
            lrun += p;
            ULL pd = pack2(p, p);
            const ULL* vr = (const ULL*)&Vs[j][0];
            #pragma unroll
            for (int i = 0; i < 32; i++) o2[i] = fma2(pd, vr[i], o2[i]);
        }
        mrun = mnew;
    }

    float inv = 1.0f / lrun;
    ULL iv = pack2(inv, inv);
    int n = nh / NH_, h = nh % NH_;
    float* dst = g_ao + ((size_t)(n * S_ + q_idx)) * C_ + h * D_;
    #pragma unroll
    for (int i = 0; i < 16; i++) {
        float2 lo = unpack2(mul2(o2[2 * i], iv));
        float2 hi = unpack2(mul2(o2[2 * i + 1], iv));
        float4 w = make_float4(lo.x, lo.y, hi.x, hi.y);
        *(float4*)(dst + i * 4) = w;
    }
}

// ---------------- output projection + bias + transpose to [N,C,H,W] -------
__global__ __launch_bounds__(256) void proj_gemm(const float* __restrict__ bias,
                                                 float* __restrict__ out) {
    __shared__ float As[64][16];    // [m][k]
    __shared__ float Bs[16][128];

    int tid = threadIdx.x;
    int m0 = blockIdx.y * 64;
    int c0 = blockIdx.x * 128;
    int n  = m0 / S_;
    int s0 = m0 % S_;
    int ty = tid / 16;
    int tx = tid % 16;

    ULL acc[4][4];
    #pragma unroll
    for (int i = 0; i < 4; i++)
        #pragma unroll
        for (int j = 0; j < 4; j++) acc[i][j] = 0ull;

    for (int k0 = 0; k0 < C_; k0 += 16) {
        __syncthreads();
        { // A tile: g_ao is [m][384], coalesce along k
            int k4 = tid % 4;
            int m  = tid / 4;
            const float* src = g_ao + (size_t)(m0 + m) * C_ + k0 + k4 * 4;
            *(float4*)&As[m][k4 * 4] = *(const float4*)src;
        }
        { // B tile: g_woutT [384][384], coalesce along c
            int r4 = tid % 32;
            int kk = tid / 32;
            #pragma unroll
            for (int p = 0; p < 2; p++) {
                const float* src = g_woutT + (size_t)(k0 + kk + p * 8) * C_ + c0 + r4 * 4;
                *(float4*)&Bs[kk + p * 8][r4 * 4] = *(const float4*)src;
            }
        }
        __syncthreads();

        #pragma unroll
        for (int k = 0; k < 16; k++) {
            float a0 = As[ty * 4 + 0][k];
            float a1 = As[ty * 4 + 1][k];
            float a2 = As[ty * 4 + 2][k];
            float a3 = As[ty * 4 + 3][k];
            ULL ad0 = pack2(a0, a0), ad1 = pack2(a1, a1);
            ULL ad2 = pack2(a2, a2), ad3 = pack2(a3, a3);
            const ULL* brow = (const ULL*)&Bs[k][tx * 8];
            ULL b0 = brow[0], b1 = brow[1], b2 = brow[2], b3 = brow[3];
            acc[0][0] = fma2(ad0, b0, acc[0][0]); acc[0][1] = fma2(ad0, b1, acc[0][1]);
            acc[0][2] = fma2(ad0, b2, acc[0][2]); acc[0][3] = fma2(ad0, b3, acc[0][3]);
            acc[1][0] = fma2(ad1, b0, acc[1][0]); acc[1][1] = fma2(ad1, b1, acc[1][1]);
            acc[1][2] = fma2(ad1, b2, acc[1][2]); acc[1][3] = fma2(ad1, b3, acc[1][3]);
            acc[2][0] = fma2(ad2, b0, acc[2][0]); acc[2][1] = fma2(ad2, b1, acc[2][1]);
            acc[2][2] = fma2(ad2, b2, acc[2][2]); acc[2][3] = fma2(ad2, b3, acc[2][3]);
            acc[3][0] = fma2(ad3, b0, acc[3][0]); acc[3][1] = fma2(ad3, b1, acc[3][1]);
            acc[3][2] = fma2(ad3, b2, acc[3][2]); acc[3][3] = fma2(ad3, b3, acc[3][3]);
        }
    }

    #pragma unroll
    for (int mi = 0; mi < 4; mi++) {
        int s = s0 + ty * 4 + mi;
        #pragma unroll
        for (int rp = 0; rp < 4; rp++) {
            float2 v = unpack2(acc[mi][rp]);
            int c = c0 + tx * 8 + rp * 2;
            out[(size_t)n * C_ * S_ + (size_t)c * S_ + s]       = v.x + bias[c];
            out[(size_t)n * C_ * S_ + (size_t)(c + 1) * S_ + s] = v.y + bias[c + 1];
        }
    }
}

// ---------------- launch ----------------
extern "C" void kernel_launch(void* const* d_in, const int* in_sizes, int n_in,
                              void* d_out, int out_size) {
    const float* x     = (const float*)d_in[0];
    const float* w_qkv = (const float*)d_in[1];
    const float* w_out = (const float*)d_in[2];
    const float* b_out = (const float*)d_in[3];
    float* out = (float*)d_out;

    transpose_wqkv<<<(C3_ * C_ + 255) / 256, 256>>>(w_qkv);
    transpose_wout<<<(C_ * C_ + 255) / 256, 256>>>(w_out);

    qkv_gemm<<<dim3(C3_ / 128, M_ / 64), 256>>>(x);

    attn_kernel<<<dim3(S_ / 128, N_ * NH_), 128>>>();

    proj_gemm<<<dim3(C_ / 128, M_ / 64), 256>>>(b_out, out);
}